// round 1
// baseline (speedup 1.0000x reference)
#include <cuda_runtime.h>
#include <math.h>
#include <stdint.h>

#define NB 8
#define NN 1000
#define NG 1000
#define NE 128
#define NDH 16
#define NKNN 16

// ---------------- scratch (static device arrays; no allocation) ----------------
__device__ float g_qgraph[NB*NE];
__device__ float g_K[NB*NN*NE];
__device__ float g_V[NB*NN*NE];
__device__ float g_q[NB*NG*NE];    // glimpse queries
__device__ float g_att[NB*NG*NE];  // attention output (pre-comb)
__device__ float g_fq[NB*NG*NE];   // final_q

// ---------------- kernel 1: graph mean + q_graph ----------------
__global__ void mean_qgraph_k(const float* __restrict__ emb, const float* __restrict__ Wqg)
{
    int b = blockIdx.x, e = threadIdx.x;
    __shared__ float sm[NE];
    const float* p = emb + (size_t)b*NN*NE + e;
    float s = 0.f;
    #pragma unroll 4
    for (int n = 0; n < NN; ++n) s += p[(size_t)n*NE];
    sm[e] = s * (1.0f/(float)NN);
    __syncthreads();
    const float4* w  = reinterpret_cast<const float4*>(Wqg + e*NE);
    const float4* m4 = reinterpret_cast<const float4*>(sm);
    float acc = 0.f;
    #pragma unroll
    for (int k = 0; k < NE/4; ++k) {
        float4 a = w[k], c = m4[k];
        acc += a.x*c.x + a.y*c.y + a.z*c.z + a.w*c.w;
    }
    g_qgraph[b*NE + e] = acc;
}

// ---------------- small GEMM: C[M x 128] = A[M x 128] @ W[128 x 128]^T ----------------
// MODE 0: plain (A indexed directly)
// MODE 1: A rows gathered via gidx (emb row = b*NN + last_node[m]); W := W + W2;
//         epilogue += g_qgraph[b*NE + n]
// MODE 2: epilogue += bias[n]
template<int MODE>
__global__ void gemm128_k(const float* __restrict__ A,
                          const float* __restrict__ W,
                          const float* __restrict__ W2,
                          const float* __restrict__ bias,
                          const int*   __restrict__ gidx,
                          float* __restrict__ C, int M)
{
    __shared__ float As[32][129];
    __shared__ float Bs[32][129];
    const int m0  = blockIdx.x * 128;
    const int tid = threadIdx.x;
    const int tx  = tid & 15, ty = tid >> 4;

    float acc[8][8];
    #pragma unroll
    for (int i = 0; i < 8; ++i)
        #pragma unroll
        for (int j = 0; j < 8; ++j) acc[i][j] = 0.f;

    for (int kc = 0; kc < NE; kc += 32) {
        // load A chunk (transposed into k-major, stride 129 => conflict-free)
        #pragma unroll
        for (int jj = 0; jj < 4; ++jj) {
            int f = tid + jj*256;
            int m = f >> 3, k4 = f & 7;
            int gm = m0 + m;
            float4 v = make_float4(0.f,0.f,0.f,0.f);
            if (gm < M) {
                long src;
                if (MODE == 1) { int b = gm / NG; src = (long)b*NN + gidx[gm]; }
                else            src = gm;
                v = *reinterpret_cast<const float4*>(A + (size_t)src*NE + kc + k4*4);
            }
            As[k4*4+0][m] = v.x; As[k4*4+1][m] = v.y;
            As[k4*4+2][m] = v.z; As[k4*4+3][m] = v.w;
        }
        // load W chunk: Bs[k][n] = W[n][kc+k] (+ W2)
        #pragma unroll
        for (int jj = 0; jj < 4; ++jj) {
            int f = tid + jj*256;
            int n = f >> 3, k4 = f & 7;
            float4 v = *reinterpret_cast<const float4*>(W + (size_t)n*NE + kc + k4*4);
            if (MODE == 1) {
                float4 v2 = *reinterpret_cast<const float4*>(W2 + (size_t)n*NE + kc + k4*4);
                v.x += v2.x; v.y += v2.y; v.z += v2.z; v.w += v2.w;
            }
            Bs[k4*4+0][n] = v.x; Bs[k4*4+1][n] = v.y;
            Bs[k4*4+2][n] = v.z; Bs[k4*4+3][n] = v.w;
        }
        __syncthreads();
        #pragma unroll
        for (int k = 0; k < 32; ++k) {
            float a[8], bb[8];
            #pragma unroll
            for (int i = 0; i < 8; ++i) a[i]  = As[k][ty + 16*i];
            #pragma unroll
            for (int i = 0; i < 8; ++i) bb[i] = Bs[k][tx + 16*i];
            #pragma unroll
            for (int i = 0; i < 8; ++i)
                #pragma unroll
                for (int j = 0; j < 8; ++j) acc[i][j] = fmaf(a[i], bb[j], acc[i][j]);
        }
        __syncthreads();
    }
    #pragma unroll
    for (int i = 0; i < 8; ++i) {
        int gm = m0 + ty + 16*i;
        if (gm >= M) continue;
        int b = gm / NG;
        #pragma unroll
        for (int j = 0; j < 8; ++j) {
            int n = tx + 16*j;
            float v = acc[i][j];
            if (MODE == 1) v += g_qgraph[b*NE + n];
            if (MODE == 2) v += bias[n];
            C[(size_t)gm*NE + n] = v;
        }
    }
}

// ---------------- decode: KNN + 16-neighbor multi-head glimpse attention ----------------
__global__ void decode_k(const int* __restrict__ last_node,
                         const float* __restrict__ coords,
                         const float* __restrict__ mask)
{
    const int b = blockIdx.x / NG, g = blockIdx.x % NG;
    const int t = threadIdx.x;
    __shared__ unsigned long long keys[1024];
    __shared__ float KshT[NE][17];
    __shared__ float VshT[NE][17];
    __shared__ float qsh[NE];
    __shared__ float attn[NE];
    __shared__ int   knn[NKNN];
    __shared__ unsigned long long wred[4];

    const size_t row = (size_t)b*NG + g;
    const int idx = last_node[row];
    qsh[t] = g_q[row*NE + t];

    const float2 lc = reinterpret_cast<const float2*>(coords)[(size_t)b*NN + idx];
    const float lsq = lc.x*lc.x + lc.y*lc.y;
    const float* mrow = mask + row*NN;
    for (int n = t; n < 1024; n += 128) {
        unsigned long long key = ~0ULL;
        if (n < NN) {
            float2 c = reinterpret_cast<const float2*>(coords)[(size_t)b*NN + n];
            float d2 = lsq + (c.x*c.x + c.y*c.y) - 2.0f*(lc.x*c.x + lc.y*c.y);
            float d = sqrtf(fmaxf(d2, 0.0f));
            if (mrow[n] == -INFINITY) d = INFINITY;
            key = ((unsigned long long)__float_as_uint(d) << 32) | (unsigned)n;
        }
        keys[n] = key;
    }
    __syncthreads();

    const int lane = t & 31, wid = t >> 5;
    for (int it = 0; it < NKNN; ++it) {
        unsigned long long best = ~0ULL;
        #pragma unroll
        for (int s = 0; s < 8; ++s) {
            unsigned long long k = keys[t + s*128];
            if (k < best) best = k;
        }
        #pragma unroll
        for (int o = 16; o > 0; o >>= 1) {
            unsigned long long v = __shfl_down_sync(0xffffffffu, best, o);
            if (v < best) best = v;
        }
        if (lane == 0) wred[wid] = best;
        __syncthreads();
        if (t == 0) {
            unsigned long long bb = wred[0];
            #pragma unroll
            for (int w = 1; w < 4; ++w) if (wred[w] < bb) bb = wred[w];
            int sel = (int)(bb & 0xffffffffULL);
            knn[it] = sel;
            keys[sel] = ~0ULL;
        }
        __syncthreads();
    }

    // load K/V rows of the 16 neighbors, transposed [e][j] (pad 17 => conflict-free)
    #pragma unroll
    for (int j = 0; j < NKNN; ++j) {
        int nj = knn[j];
        KshT[t][j] = g_K[((size_t)b*NN + nj)*NE + t];
        VshT[t][j] = g_V[((size_t)b*NN + nj)*NE + t];
    }
    __syncthreads();

    // scores: thread t => head h=t>>4, neighbor j=t&15
    {
        const int h = t >> 4, j = t & 15;
        float s = 0.f;
        #pragma unroll
        for (int d = 0; d < NDH; ++d)
            s = fmaf(qsh[h*NDH + d], KshT[h*NDH + d][j], s);
        s *= 0.25f;                                  // 1/sqrt(DH)
        float mx = s;
        #pragma unroll
        for (int o = 8; o > 0; o >>= 1) mx = fmaxf(mx, __shfl_xor_sync(0xffffffffu, mx, o));
        float p = expf(s - mx);
        float sum = p;
        #pragma unroll
        for (int o = 8; o > 0; o >>= 1) sum += __shfl_xor_sync(0xffffffffu, sum, o);
        attn[t] = p / sum;
    }
    __syncthreads();

    // out[e] = sum_j attn[h(e)][j] * V[nj][e]
    float o_acc = 0.f;
    const int hb = t & ~15;
    #pragma unroll
    for (int jj = 0; jj < NKNN; ++jj)
        o_acc = fmaf(attn[hb + jj], VshT[t][jj], o_acc);
    g_att[row*NE + t] = o_acc;
}

// ---------------- big GEMM: s = 10*tanh(final_q . emb / sqrt(E)) + mask ----------------
__global__ void score_gemm_k(const float* __restrict__ fq, const float* __restrict__ emb,
                             const float* __restrict__ mask, float* __restrict__ outp)
{
    __shared__ float As[32][129];
    __shared__ float Bs[32][129];
    const int b  = blockIdx.z;
    const int m0 = blockIdx.y * 128;
    const int n0 = blockIdx.x * 128;
    const float* A  = fq  + (size_t)b*NG*NE;
    const float* Bm = emb + (size_t)b*NN*NE;
    const int tid = threadIdx.x;
    const int tx  = tid & 15, ty = tid >> 4;

    float acc[8][8];
    #pragma unroll
    for (int i = 0; i < 8; ++i)
        #pragma unroll
        for (int j = 0; j < 8; ++j) acc[i][j] = 0.f;

    for (int kc = 0; kc < NE; kc += 32) {
        #pragma unroll
        for (int jj = 0; jj < 4; ++jj) {
            int f = tid + jj*256;
            int m = f >> 3, k4 = f & 7;
            int gm = m0 + m;
            float4 v = make_float4(0.f,0.f,0.f,0.f);
            if (gm < NG) v = *reinterpret_cast<const float4*>(A + (size_t)gm*NE + kc + k4*4);
            As[k4*4+0][m] = v.x; As[k4*4+1][m] = v.y;
            As[k4*4+2][m] = v.z; As[k4*4+3][m] = v.w;
        }
        #pragma unroll
        for (int jj = 0; jj < 4; ++jj) {
            int f = tid + jj*256;
            int n = f >> 3, k4 = f & 7;
            int gn = n0 + n;
            float4 v = make_float4(0.f,0.f,0.f,0.f);
            if (gn < NN) v = *reinterpret_cast<const float4*>(Bm + (size_t)gn*NE + kc + k4*4);
            Bs[k4*4+0][n] = v.x; Bs[k4*4+1][n] = v.y;
            Bs[k4*4+2][n] = v.z; Bs[k4*4+3][n] = v.w;
        }
        __syncthreads();
        #pragma unroll
        for (int k = 0; k < 32; ++k) {
            float a[8], bb[8];
            #pragma unroll
            for (int i = 0; i < 8; ++i) a[i]  = As[k][ty + 16*i];
            #pragma unroll
            for (int i = 0; i < 8; ++i) bb[i] = Bs[k][tx + 16*i];
            #pragma unroll
            for (int i = 0; i < 8; ++i)
                #pragma unroll
                for (int j = 0; j < 8; ++j) acc[i][j] = fmaf(a[i], bb[j], acc[i][j]);
        }
        __syncthreads();
    }
    const float rsE = 0.08838834764831845f;  // 1/sqrt(128)
    #pragma unroll
    for (int i = 0; i < 8; ++i) {
        int gm = m0 + ty + 16*i;
        if (gm >= NG) continue;
        #pragma unroll
        for (int j = 0; j < 8; ++j) {
            int gn = n0 + tx + 16*j;
            if (gn >= NN) continue;
            size_t off = ((size_t)b*NG + gm)*NN + gn;
            outp[off] = 10.0f*tanhf(acc[i][j]*rsE) + mask[off];
        }
    }
}

// ---------------- row softmax over N (in-place on d_out), warp per row ----------------
__global__ void softmax_k(float* __restrict__ outp)
{
    const int warp = threadIdx.x >> 5, lane = threadIdx.x & 31;
    const size_t row = (size_t)blockIdx.x * 8 + warp;
    float* p = outp + row*NN;
    float v[32];
    float mx = -INFINITY;
    #pragma unroll
    for (int i = 0; i < 32; ++i) {
        int n = lane + 32*i;
        v[i] = (n < NN) ? p[n] : -INFINITY;
        mx = fmaxf(mx, v[i]);
    }
    #pragma unroll
    for (int o = 16; o > 0; o >>= 1) mx = fmaxf(mx, __shfl_xor_sync(0xffffffffu, mx, o));
    float s = 0.f;
    #pragma unroll
    for (int i = 0; i < 32; ++i) {
        int n = lane + 32*i;
        float e = (n < NN) ? expf(v[i] - mx) : 0.f;
        v[i] = e; s += e;
    }
    #pragma unroll
    for (int o = 16; o > 0; o >>= 1) s += __shfl_xor_sync(0xffffffffu, s, o);
    const float inv = 1.0f / s;
    #pragma unroll
    for (int i = 0; i < 32; ++i) {
        int n = lane + 32*i;
        if (n < NN) p[n] = v[i]*inv;
    }
}

// ---------------- launch ----------------
extern "C" void kernel_launch(void* const* d_in, const int* in_sizes, int n_in,
                              void* d_out, int out_size)
{
    const int*   last_node = (const int*)  d_in[0];
    const float* coords    = (const float*)d_in[1];
    const float* emb       = (const float*)d_in[2];
    const float* mask      = (const float*)d_in[3];
    const float* Wqg       = (const float*)d_in[4];
    const float* Wq1       = (const float*)d_in[5];
    const float* Wq2       = (const float*)d_in[6];
    const float* Wk        = (const float*)d_in[7];
    const float* Wv        = (const float*)d_in[8];
    const float* Wc        = (const float*)d_in[9];
    const float* bc        = (const float*)d_in[10];
    float* outp = (float*)d_out;

    float *pK, *pV, *pq, *patt, *pfq;
    cudaGetSymbolAddress((void**)&pK,   g_K);
    cudaGetSymbolAddress((void**)&pV,   g_V);
    cudaGetSymbolAddress((void**)&pq,   g_q);
    cudaGetSymbolAddress((void**)&patt, g_att);
    cudaGetSymbolAddress((void**)&pfq,  g_fq);

    const int Mrows = NB*NG;                 // 8000
    const int gB = (Mrows + 127) / 128;      // 63

    mean_qgraph_k<<<NB, 128>>>(emb, Wqg);
    gemm128_k<0><<<gB, 256>>>(emb, Wk, nullptr, nullptr, nullptr, pK, NB*NN);
    gemm128_k<0><<<gB, 256>>>(emb, Wv, nullptr, nullptr, nullptr, pV, NB*NN);
    gemm128_k<1><<<gB, 256>>>(emb, Wq1, Wq2, nullptr, last_node, pq, Mrows);
    decode_k<<<NB*NG, 128>>>(last_node, coords, mask);
    gemm128_k<2><<<gB, 256>>>(patt, Wc, nullptr, bc, nullptr, pfq, Mrows);
    score_gemm_k<<<dim3(8, 8, NB), 256>>>(pfq, emb, mask, outp);
    softmax_k<<<NB*NG/8, 256>>>(outp);
}

// round 2
// speedup vs baseline: 1.2438x; 1.2438x over previous
#include <cuda_runtime.h>
#include <math.h>
#include <stdint.h>

#define NB 8
#define NN 1000
#define NG 1000
#define NE 128
#define NDH 16
#define NKNN 16

typedef unsigned long long ull;

// ---------------- scratch (static device arrays; no allocation) ----------------
__device__ float g_part[64*NE];
__device__ float g_qgraph[NB*NE];
__device__ float g_K[NB*NN*NE];
__device__ float g_V[NB*NN*NE];
__device__ float g_q[NB*NG*NE];    // glimpse queries
__device__ float g_att[NB*NG*NE];  // attention output (pre-comb)
__device__ float g_fq[NB*NG*NE];   // final_q

// packed dual-FMA: d = a*b + d elementwise on two fp32 lanes (exact fp32)
__device__ __forceinline__ void fma2(ull &d, ull a, ull b) {
    asm("fma.rn.f32x2 %0, %1, %2, %0;" : "+l"(d) : "l"(a), "l"(b));
}

// ---------------- mean: partial sums over n-chunks ----------------
__global__ void mean_part_k(const float* __restrict__ emb)
{
    const int b = blockIdx.x >> 3, c = blockIdx.x & 7;
    const int e = threadIdx.x;
    const float* p = emb + ((size_t)b*NN + c*125)*NE + e;
    float s = 0.f;
    #pragma unroll 5
    for (int i = 0; i < 125; ++i) s += p[(size_t)i*NE];
    g_part[blockIdx.x*NE + e] = s;
}

// ---------------- q_graph = Wqg @ mean ----------------
__global__ void qgraph_k(const float* __restrict__ Wqg)
{
    const int b = blockIdx.x, e = threadIdx.x;
    __shared__ float sm[NE];
    float s = 0.f;
    #pragma unroll
    for (int c = 0; c < 8; ++c) s += g_part[(b*8 + c)*NE + e];
    sm[e] = s * (1.0f/(float)NN);
    __syncthreads();
    const float4* w  = reinterpret_cast<const float4*>(Wqg + e*NE);
    const float4* m4 = reinterpret_cast<const float4*>(sm);
    float acc = 0.f;
    #pragma unroll
    for (int k = 0; k < NE/4; ++k) {
        float4 a = w[k], c = m4[k];
        acc += a.x*c.x + a.y*c.y + a.z*c.z + a.w*c.w;
    }
    g_qgraph[b*NE + e] = acc;
}

// ---------------- fused 128x128 projection GEMMs, FFMA2 inner loop ----------------
// mode = mode_base + blockIdx.y:
//   0: g_K  = emb @ Wk^T
//   1: g_V  = emb @ Wv^T
//   2: g_q  = gather(emb,last_node) @ (Wq1+Wq2)^T + q_graph
//   3: g_fq = g_att @ Wc^T + bc
__global__ void __launch_bounds__(256,2) gemm128_k(
    const float* __restrict__ emb, const int* __restrict__ gidx,
    const float* __restrict__ Wk,  const float* __restrict__ Wv,
    const float* __restrict__ Wq1, const float* __restrict__ Wq2,
    const float* __restrict__ Wc,  const float* __restrict__ bc,
    int mode_base)
{
    const int mode = mode_base + blockIdx.y;
    const float* A; const float* W; const float* W2 = nullptr; float* C;
    if      (mode == 0) { A = emb;   W = Wk;  C = g_K;  }
    else if (mode == 1) { A = emb;   W = Wv;  C = g_V;  }
    else if (mode == 2) { A = emb;   W = Wq1; W2 = Wq2; C = g_q; }
    else                { A = g_att; W = Wc;  C = g_fq; }

    __shared__ __align__(16) float As[32][130];
    __shared__ __align__(16) float Bs[32][260];   // value-duplicated along n

    const int m0  = blockIdx.x * 128;
    const int tid = threadIdx.x;
    const int tx  = tid & 15, ty = tid >> 4;
    const int M   = NB*NG;   // 8000 (same for all modes)

    ull acc[4][8];
    #pragma unroll
    for (int p = 0; p < 4; ++p)
        #pragma unroll
        for (int q = 0; q < 8; ++q) acc[p][q] = 0ULL;

    for (int kc = 0; kc < NE; kc += 32) {
        #pragma unroll
        for (int jj = 0; jj < 4; ++jj) {
            int f = tid + jj*256;
            int m = f >> 3, kq = f & 7;
            int gm = m0 + m;
            float4 v = make_float4(0.f,0.f,0.f,0.f);
            if (gm < M) {
                size_t src;
                if (mode == 2) { int b = gm / NG; src = (size_t)b*NN + gidx[gm]; }
                else            src = (size_t)gm;
                v = *reinterpret_cast<const float4*>(A + src*NE + kc + kq*4);
            }
            As[kq*4+0][m] = v.x; As[kq*4+1][m] = v.y;
            As[kq*4+2][m] = v.z; As[kq*4+3][m] = v.w;
        }
        #pragma unroll
        for (int jj = 0; jj < 4; ++jj) {
            int f = tid + jj*256;
            int n = f >> 3, kq = f & 7;
            float4 v = *reinterpret_cast<const float4*>(W + (size_t)n*NE + kc + kq*4);
            if (mode == 2) {
                float4 v2 = *reinterpret_cast<const float4*>(W2 + (size_t)n*NE + kc + kq*4);
                v.x += v2.x; v.y += v2.y; v.z += v2.z; v.w += v2.w;
            }
            *reinterpret_cast<float2*>(&Bs[kq*4+0][2*n]) = make_float2(v.x, v.x);
            *reinterpret_cast<float2*>(&Bs[kq*4+1][2*n]) = make_float2(v.y, v.y);
            *reinterpret_cast<float2*>(&Bs[kq*4+2][2*n]) = make_float2(v.z, v.z);
            *reinterpret_cast<float2*>(&Bs[kq*4+3][2*n]) = make_float2(v.w, v.w);
        }
        __syncthreads();
        #pragma unroll
        for (int k = 0; k < 32; ++k) {
            ull a[4], b[8];
            #pragma unroll
            for (int p = 0; p < 4; ++p)
                a[p] = *reinterpret_cast<const ull*>(&As[k][ty*2 + 32*p]);
            #pragma unroll
            for (int q = 0; q < 8; ++q)
                b[q] = *reinterpret_cast<const ull*>(&Bs[k][2*(tx + 16*q)]);
            #pragma unroll
            for (int p = 0; p < 4; ++p)
                #pragma unroll
                for (int q = 0; q < 8; ++q) fma2(acc[p][q], a[p], b[q]);
        }
        __syncthreads();
    }

    #pragma unroll
    for (int p = 0; p < 4; ++p) {
        int m = ty*2 + 32*p;
        int gm = m0 + m;
        if (gm + 1 >= M + 1) {}           // keep structure simple; guard below
        #pragma unroll
        for (int q = 0; q < 8; ++q) {
            int n = tx + 16*q;
            float lo = __uint_as_float((unsigned)(acc[p][q] & 0xffffffffULL));
            float hi = __uint_as_float((unsigned)(acc[p][q] >> 32));
            if (gm < M) {
                float v = lo;
                if (mode == 2) v += g_qgraph[(gm/NG)*NE + n];
                if (mode == 3) v += bc[n];
                C[(size_t)gm*NE + n] = v;
            }
            if (gm + 1 < M) {
                float v = hi;
                if (mode == 2) v += g_qgraph[((gm+1)/NG)*NE + n];
                if (mode == 3) v += bc[n];
                C[(size_t)(gm+1)*NE + n] = v;
            }
        }
    }
}

// ---------------- decode: hierarchical register top-16 + glimpse attention ----------------
__device__ __forceinline__ ull warp_min_u64(ull v) {
    #pragma unroll
    for (int o = 16; o > 0; o >>= 1) {
        ull u = __shfl_xor_sync(0xffffffffu, v, o);
        if (u < v) v = u;
    }
    return v;
}

__global__ void decode_k(const int* __restrict__ last_node,
                         const float* __restrict__ coords,
                         const float* __restrict__ mask)
{
    const int b = blockIdx.x / NG, g = blockIdx.x % NG;
    const int t = threadIdx.x;
    const int lane = t & 31, w = t >> 5;
    __shared__ float KshT[NE][17];
    __shared__ float VshT[NE][17];
    __shared__ float qsh[NE];
    __shared__ float attn[NE];
    __shared__ int   knn[NKNN];
    __shared__ ull   cand[64];

    const size_t row = (size_t)b*NG + g;
    const int idx = last_node[row];
    qsh[t] = g_q[row*NE + t];

    const float2 lc = reinterpret_cast<const float2*>(coords)[(size_t)b*NN + idx];
    const float lsq = lc.x*lc.x + lc.y*lc.y;
    const float* mrow = mask + row*NN;

    ull kk[8];
    #pragma unroll
    for (int s = 0; s < 8; ++s) {
        int n = t + 128*s;
        ull key = ~0ULL;
        if (n < NN) {
            float2 c = reinterpret_cast<const float2*>(coords)[(size_t)b*NN + n];
            float d2 = lsq + (c.x*c.x + c.y*c.y) - 2.0f*(lc.x*c.x + lc.y*c.y);
            float d = sqrtf(fmaxf(d2, 0.0f));
            if (mrow[n] == -INFINITY) d = INFINITY;
            key = ((ull)__float_as_uint(d) << 32) | (unsigned)n;
        }
        kk[s] = key;
    }

    // per-warp top-16 (no barriers; keys unique => exactly one winner lane)
    for (int r = 0; r < NKNN; ++r) {
        ull lb = ~0ULL; int li = 0;
        #pragma unroll
        for (int s = 0; s < 8; ++s) if (kk[s] < lb) { lb = kk[s]; li = s; }
        ull wb = warp_min_u64(lb);
        if (lb == wb) kk[li] = ~0ULL;
        if (lane == 0) cand[w*16 + r] = wb;
    }
    __syncthreads();

    // warp 0 merges 64 candidates into global top-16
    if (w == 0) {
        ull c0 = cand[lane], c1 = cand[lane + 32];
        for (int r = 0; r < NKNN; ++r) {
            ull lb = c0 < c1 ? c0 : c1;
            ull wb = warp_min_u64(lb);
            if (wb == c0) c0 = ~0ULL;
            else if (wb == c1) c1 = ~0ULL;
            if (lane == 0) knn[r] = (int)(wb & 0xffffffffULL);
        }
    }
    __syncthreads();

    // K/V rows of 16 neighbors, transposed [e][j]
    #pragma unroll
    for (int j = 0; j < NKNN; ++j) {
        int nj = knn[j];
        KshT[t][j] = g_K[((size_t)b*NN + nj)*NE + t];
        VshT[t][j] = g_V[((size_t)b*NN + nj)*NE + t];
    }
    __syncthreads();

    // scores: thread t => head h=t>>4, neighbor j=t&15; 16-wide softmax per head
    {
        const int h = t >> 4;
        const int j = t & 15;
        float s = 0.f;
        #pragma unroll
        for (int d = 0; d < NDH; ++d)
            s = fmaf(qsh[h*NDH + d], KshT[h*NDH + d][j], s);
        s *= 0.25f;
        float mx = s;
        #pragma unroll
        for (int o = 8; o > 0; o >>= 1) mx = fmaxf(mx, __shfl_xor_sync(0xffffffffu, mx, o));
        float p = expf(s - mx);
        float sum = p;
        #pragma unroll
        for (int o = 8; o > 0; o >>= 1) sum += __shfl_xor_sync(0xffffffffu, sum, o);
        attn[t] = p / sum;
    }
    __syncthreads();

    float o_acc = 0.f;
    const int hb = t & ~15;
    #pragma unroll
    for (int jj = 0; jj < NKNN; ++jj)
        o_acc = fmaf(attn[hb + jj], VshT[t][jj], o_acc);
    g_att[row*NE + t] = o_acc;
}

// ---------------- score GEMM: s = 10*tanh(final_q . emb / sqrt(E)) + mask ----------------
__global__ void __launch_bounds__(256,2) score_gemm_k(
    const float* __restrict__ emb, const float* __restrict__ mask,
    float* __restrict__ outp)
{
    __shared__ __align__(16) float As[32][130];
    __shared__ __align__(16) float Bs[32][260];
    const int b  = blockIdx.z;
    const int m0 = blockIdx.y * 128;
    const int n0 = blockIdx.x * 128;
    const float* A  = g_fq + (size_t)b*NG*NE;
    const float* Bm = emb  + (size_t)b*NN*NE;
    const int tid = threadIdx.x;
    const int tx  = tid & 15, ty = tid >> 4;

    ull acc[4][8];
    #pragma unroll
    for (int p = 0; p < 4; ++p)
        #pragma unroll
        for (int q = 0; q < 8; ++q) acc[p][q] = 0ULL;

    for (int kc = 0; kc < NE; kc += 32) {
        #pragma unroll
        for (int jj = 0; jj < 4; ++jj) {
            int f = tid + jj*256;
            int m = f >> 3, kq = f & 7;
            int gm = m0 + m;
            float4 v = make_float4(0.f,0.f,0.f,0.f);
            if (gm < NG) v = *reinterpret_cast<const float4*>(A + (size_t)gm*NE + kc + kq*4);
            As[kq*4+0][m] = v.x; As[kq*4+1][m] = v.y;
            As[kq*4+2][m] = v.z; As[kq*4+3][m] = v.w;
        }
        #pragma unroll
        for (int jj = 0; jj < 4; ++jj) {
            int f = tid + jj*256;
            int n = f >> 3, kq = f & 7;
            int gn = n0 + n;
            float4 v = make_float4(0.f,0.f,0.f,0.f);
            if (gn < NN) v = *reinterpret_cast<const float4*>(Bm + (size_t)gn*NE + kc + kq*4);
            *reinterpret_cast<float2*>(&Bs[kq*4+0][2*n]) = make_float2(v.x, v.x);
            *reinterpret_cast<float2*>(&Bs[kq*4+1][2*n]) = make_float2(v.y, v.y);
            *reinterpret_cast<float2*>(&Bs[kq*4+2][2*n]) = make_float2(v.z, v.z);
            *reinterpret_cast<float2*>(&Bs[kq*4+3][2*n]) = make_float2(v.w, v.w);
        }
        __syncthreads();
        #pragma unroll
        for (int k = 0; k < 32; ++k) {
            ull a[4], bb[8];
            #pragma unroll
            for (int p = 0; p < 4; ++p)
                a[p] = *reinterpret_cast<const ull*>(&As[k][ty*2 + 32*p]);
            #pragma unroll
            for (int q = 0; q < 8; ++q)
                bb[q] = *reinterpret_cast<const ull*>(&Bs[k][2*(tx + 16*q)]);
            #pragma unroll
            for (int p = 0; p < 4; ++p)
                #pragma unroll
                for (int q = 0; q < 8; ++q) fma2(acc[p][q], a[p], bb[q]);
        }
        __syncthreads();
    }

    const float rsE = 0.08838834764831845f;  // 1/sqrt(128)
    #pragma unroll
    for (int p = 0; p < 4; ++p) {
        int gm = m0 + ty*2 + 32*p;
        #pragma unroll
        for (int q = 0; q < 8; ++q) {
            int gn = n0 + tx + 16*q;
            if (gn >= NN) continue;
            float lo = __uint_as_float((unsigned)(acc[p][q] & 0xffffffffULL));
            float hi = __uint_as_float((unsigned)(acc[p][q] >> 32));
            if (gm < NG) {
                size_t off = ((size_t)b*NG + gm)*NN + gn;
                outp[off] = 10.0f*tanhf(lo*rsE) + mask[off];
            }
            if (gm + 1 < NG) {
                size_t off = ((size_t)b*NG + gm + 1)*NN + gn;
                outp[off] = 10.0f*tanhf(hi*rsE) + mask[off];
            }
        }
    }
}

// ---------------- row softmax over N (in-place on d_out), warp per row ----------------
__global__ void softmax_k(float* __restrict__ outp)
{
    const int warp = threadIdx.x >> 5, lane = threadIdx.x & 31;
    const size_t row = (size_t)blockIdx.x * 8 + warp;
    float* p = outp + row*NN;
    float v[32];
    float mx = -INFINITY;
    #pragma unroll
    for (int i = 0; i < 32; ++i) {
        int n = lane + 32*i;
        v[i] = (n < NN) ? p[n] : -INFINITY;
        mx = fmaxf(mx, v[i]);
    }
    #pragma unroll
    for (int o = 16; o > 0; o >>= 1) mx = fmaxf(mx, __shfl_xor_sync(0xffffffffu, mx, o));
    float s = 0.f;
    #pragma unroll
    for (int i = 0; i < 32; ++i) {
        int n = lane + 32*i;
        float e = (n < NN) ? expf(v[i] - mx) : 0.f;
        v[i] = e; s += e;
    }
    #pragma unroll
    for (int o = 16; o > 0; o >>= 1) s += __shfl_xor_sync(0xffffffffu, s, o);
    const float inv = 1.0f / s;
    #pragma unroll
    for (int i = 0; i < 32; ++i) {
        int n = lane + 32*i;
        if (n < NN) p[n] = v[i]*inv;
    }
}

// ---------------- launch ----------------
extern "C" void kernel_launch(void* const* d_in, const int* in_sizes, int n_in,
                              void* d_out, int out_size)
{
    const int*   last_node = (const int*)  d_in[0];
    const float* coords    = (const float*)d_in[1];
    const float* emb       = (const float*)d_in[2];
    const float* mask      = (const float*)d_in[3];
    const float* Wqg       = (const float*)d_in[4];
    const float* Wq1       = (const float*)d_in[5];
    const float* Wq2       = (const float*)d_in[6];
    const float* Wk        = (const float*)d_in[7];
    const float* Wv        = (const float*)d_in[8];
    const float* Wc        = (const float*)d_in[9];
    const float* bc        = (const float*)d_in[10];
    float* outp = (float*)d_out;

    mean_part_k<<<64, 128>>>(emb);
    qgraph_k<<<NB, 128>>>(Wqg);
    gemm128_k<<<dim3(63, 3), 256>>>(emb, last_node, Wk, Wv, Wq1, Wq2, Wc, bc, 0);
    decode_k<<<NB*NG, 128>>>(last_node, coords, mask);
    gemm128_k<<<dim3(63, 1), 256>>>(emb, last_node, Wk, Wv, Wq1, Wq2, Wc, bc, 3);
    score_gemm_k<<<dim3(8, 8, NB), 256>>>(emb, mask, outp);
    softmax_k<<<NB*NG/8, 256>>>(outp);
}

// round 3
// speedup vs baseline: 1.4768x; 1.1873x over previous
#include <cuda_runtime.h>
#include <math.h>
#include <stdint.h>

#define NB 8
#define NN 1000
#define NG 1000
#define NE 128
#define NDH 16
#define NKNN 16

typedef unsigned long long ull;

// ---------------- scratch (static device arrays; no allocation) ----------------
__device__ float g_part[64*NE];
__device__ float g_qgraph[NB*NE];
__device__ float g_K[NB*NN*NE];
__device__ float g_V[NB*NN*NE];
__device__ float g_q[NB*NG*NE];    // glimpse queries
__device__ float g_att[NB*NG*NE];  // attention output (pre-comb)
__device__ float g_fq[NB*NG*NE];   // final_q

// packed dual-FMA: d = a*b + d elementwise on two fp32 lanes (exact fp32)
__device__ __forceinline__ void fma2(ull &d, ull a, ull b) {
    asm("fma.rn.f32x2 %0, %1, %2, %0;" : "+l"(d) : "l"(a), "l"(b));
}

__device__ __forceinline__ unsigned redux_min_u32(unsigned v) {
    unsigned r;
    asm("redux.sync.min.u32 %0, %1, 0xffffffff;" : "=r"(r) : "r"(v));
    return r;
}

// 10*tanh(x) = 10 - 20/(e^{2x}+1); saturates correctly via __expf inf/0
__device__ __forceinline__ float tanh10(float x) {
    float e = __expf(2.0f*x);
    return 10.0f - __fdividef(20.0f, e + 1.0f);
}

// ---------------- mean: partial sums over n-chunks ----------------
__global__ void mean_part_k(const float* __restrict__ emb)
{
    const int b = blockIdx.x >> 3, c = blockIdx.x & 7;
    const int e = threadIdx.x;
    const float* p = emb + ((size_t)b*NN + c*125)*NE + e;
    float s = 0.f;
    #pragma unroll 5
    for (int i = 0; i < 125; ++i) s += p[(size_t)i*NE];
    g_part[blockIdx.x*NE + e] = s;
}

// ---------------- q_graph = Wqg @ mean ----------------
__global__ void qgraph_k(const float* __restrict__ Wqg)
{
    const int b = blockIdx.x, e = threadIdx.x;
    __shared__ float sm[NE];
    float s = 0.f;
    #pragma unroll
    for (int c = 0; c < 8; ++c) s += g_part[(b*8 + c)*NE + e];
    sm[e] = s * (1.0f/(float)NN);
    __syncthreads();
    const float4* w  = reinterpret_cast<const float4*>(Wqg + e*NE);
    const float4* m4 = reinterpret_cast<const float4*>(sm);
    float acc = 0.f;
    #pragma unroll
    for (int k = 0; k < NE/4; ++k) {
        float4 a = w[k], c = m4[k];
        acc += a.x*c.x + a.y*c.y + a.z*c.z + a.w*c.w;
    }
    g_qgraph[b*NE + e] = acc;
}

// ---------------- fused 128x128 projection GEMMs, FFMA2 inner loop ----------------
__global__ void __launch_bounds__(256,2) gemm128_k(
    const float* __restrict__ emb, const int* __restrict__ gidx,
    const float* __restrict__ Wk,  const float* __restrict__ Wv,
    const float* __restrict__ Wq1, const float* __restrict__ Wq2,
    const float* __restrict__ Wc,  const float* __restrict__ bc,
    int mode_base)
{
    const int mode = mode_base + blockIdx.y;
    const float* A; const float* W; const float* W2 = nullptr; float* C;
    if      (mode == 0) { A = emb;   W = Wk;  C = g_K;  }
    else if (mode == 1) { A = emb;   W = Wv;  C = g_V;  }
    else if (mode == 2) { A = emb;   W = Wq1; W2 = Wq2; C = g_q; }
    else                { A = g_att; W = Wc;  C = g_fq; }

    __shared__ __align__(16) float As[32][130];
    __shared__ __align__(16) float Bs[32][260];   // value-duplicated along n

    const int m0  = blockIdx.x * 128;
    const int tid = threadIdx.x;
    const int tx  = tid & 15, ty = tid >> 4;
    const int M   = NB*NG;   // 8000

    ull acc[4][8];
    #pragma unroll
    for (int p = 0; p < 4; ++p)
        #pragma unroll
        for (int q = 0; q < 8; ++q) acc[p][q] = 0ULL;

    for (int kc = 0; kc < NE; kc += 32) {
        #pragma unroll
        for (int jj = 0; jj < 4; ++jj) {
            int f = tid + jj*256;
            int m = f >> 3, kq = f & 7;
            int gm = m0 + m;
            float4 v = make_float4(0.f,0.f,0.f,0.f);
            if (gm < M) {
                size_t src;
                if (mode == 2) { int b = gm / NG; src = (size_t)b*NN + gidx[gm]; }
                else            src = (size_t)gm;
                v = *reinterpret_cast<const float4*>(A + src*NE + kc + kq*4);
            }
            As[kq*4+0][m] = v.x; As[kq*4+1][m] = v.y;
            As[kq*4+2][m] = v.z; As[kq*4+3][m] = v.w;
        }
        #pragma unroll
        for (int jj = 0; jj < 4; ++jj) {
            int f = tid + jj*256;
            int n = f >> 3, kq = f & 7;
            float4 v = *reinterpret_cast<const float4*>(W + (size_t)n*NE + kc + kq*4);
            if (mode == 2) {
                float4 v2 = *reinterpret_cast<const float4*>(W2 + (size_t)n*NE + kc + kq*4);
                v.x += v2.x; v.y += v2.y; v.z += v2.z; v.w += v2.w;
            }
            *reinterpret_cast<float2*>(&Bs[kq*4+0][2*n]) = make_float2(v.x, v.x);
            *reinterpret_cast<float2*>(&Bs[kq*4+1][2*n]) = make_float2(v.y, v.y);
            *reinterpret_cast<float2*>(&Bs[kq*4+2][2*n]) = make_float2(v.z, v.z);
            *reinterpret_cast<float2*>(&Bs[kq*4+3][2*n]) = make_float2(v.w, v.w);
        }
        __syncthreads();
        #pragma unroll
        for (int k = 0; k < 32; ++k) {
            ull a[4], b[8];
            #pragma unroll
            for (int p = 0; p < 4; ++p)
                a[p] = *reinterpret_cast<const ull*>(&As[k][ty*2 + 32*p]);
            #pragma unroll
            for (int q = 0; q < 8; ++q)
                b[q] = *reinterpret_cast<const ull*>(&Bs[k][2*(tx + 16*q)]);
            #pragma unroll
            for (int p = 0; p < 4; ++p)
                #pragma unroll
                for (int q = 0; q < 8; ++q) fma2(acc[p][q], a[p], b[q]);
        }
        __syncthreads();
    }

    #pragma unroll
    for (int p = 0; p < 4; ++p) {
        int gm = m0 + ty*2 + 32*p;
        #pragma unroll
        for (int q = 0; q < 8; ++q) {
            int n = tx + 16*q;
            float lo = __uint_as_float((unsigned)(acc[p][q] & 0xffffffffULL));
            float hi = __uint_as_float((unsigned)(acc[p][q] >> 32));
            if (gm < M) {
                float v = lo;
                if (mode == 2) v += g_qgraph[(gm/NG)*NE + n];
                if (mode == 3) v += bc[n];
                C[(size_t)gm*NE + n] = v;
            }
            if (gm + 1 < M) {
                float v = hi;
                if (mode == 2) v += g_qgraph[((gm+1)/NG)*NE + n];
                if (mode == 3) v += bc[n];
                C[(size_t)(gm+1)*NE + n] = v;
            }
        }
    }
}

// ---------------- decode: redux-based top-16 + glimpse attention ----------------
__global__ void decode_k(const int* __restrict__ last_node,
                         const float* __restrict__ coords,
                         const float* __restrict__ mask)
{
    const int b = blockIdx.x / NG, g = blockIdx.x % NG;
    const int t = threadIdx.x;
    const int lane = t & 31, w = t >> 5;
    __shared__ float KshT[NE][17];
    __shared__ float VshT[NE][17];
    __shared__ float qsh[NE];
    __shared__ float attn[NE];
    __shared__ int   knn[NKNN];
    __shared__ unsigned cand_db[64];
    __shared__ unsigned cand_ix[64];

    const size_t row = (size_t)b*NG + g;
    const int idx = last_node[row];
    qsh[t] = g_q[row*NE + t];

    const float2 lc = reinterpret_cast<const float2*>(coords)[(size_t)b*NN + idx];
    const float lsq = lc.x*lc.x + lc.y*lc.y;
    const float* mrow = mask + row*NN;

    // distance bits per lane-slot; index n = t + 128*s
    unsigned db[8];
    #pragma unroll
    for (int s = 0; s < 8; ++s) {
        int n = t + 128*s;
        unsigned key = 0xFFFFFFFFu;
        if (n < NN) {
            float2 c = reinterpret_cast<const float2*>(coords)[(size_t)b*NN + n];
            float d2 = lsq + (c.x*c.x + c.y*c.y) - 2.0f*(lc.x*c.x + lc.y*c.y);
            float d = sqrtf(fmaxf(d2, 0.0f));
            if (mrow[n] == -INFINITY) d = INFINITY;
            key = __float_as_uint(d);      // d >= 0 => bits monotone
        }
        db[s] = key;
    }

    // per-warp top-16 via redux.sync.min.u32 (dist, then index tie-break)
    for (int r = 0; r < NKNN; ++r) {
        unsigned ld = 0xFFFFFFFFu; unsigned ln = 0xFFFFFFFFu;
        #pragma unroll
        for (int s = 0; s < 8; ++s)
            if (db[s] < ld) { ld = db[s]; ln = (unsigned)(t + 128*s); }
        unsigned wmin = redux_min_u32(ld);
        unsigned cand = (ld == wmin) ? ln : 0xFFFFFFFFu;
        unsigned widx = redux_min_u32(cand);
        if (cand == widx) {                    // winner lane consumes (first match)
            bool done = false;
            #pragma unroll
            for (int s = 0; s < 8; ++s)
                if (!done && db[s] == ld) { db[s] = 0xFFFFFFFFu; done = true; }
        }
        if (lane == 0) { cand_db[w*16 + r] = wmin; cand_ix[w*16 + r] = widx; }
    }
    __syncthreads();

    // warp 0 merges 64 candidates into global top-16 (same redux trick)
    if (w == 0) {
        unsigned d0 = cand_db[lane],      i0 = cand_ix[lane];
        unsigned d1 = cand_db[lane + 32], i1 = cand_ix[lane + 32];
        for (int r = 0; r < NKNN; ++r) {
            bool take1 = (d1 < d0) || (d1 == d0 && i1 < i0);
            unsigned ld = take1 ? d1 : d0;
            unsigned li = take1 ? i1 : i0;
            unsigned wmin = redux_min_u32(ld);
            unsigned cand = (ld == wmin) ? li : 0xFFFFFFFFu;
            unsigned widx = redux_min_u32(cand);
            if (cand == widx) {
                if (take1) { d1 = 0xFFFFFFFFu; i1 = 0xFFFFFFFFu; }
                else       { d0 = 0xFFFFFFFFu; i0 = 0xFFFFFFFFu; }
            }
            if (lane == 0) knn[r] = (int)widx;
        }
    }
    __syncthreads();

    // K/V rows of 16 neighbors, transposed [e][j] (pad 17 => conflict-free)
    #pragma unroll
    for (int j = 0; j < NKNN; ++j) {
        int nj = knn[j];
        KshT[t][j] = g_K[((size_t)b*NN + nj)*NE + t];
        VshT[t][j] = g_V[((size_t)b*NN + nj)*NE + t];
    }
    __syncthreads();

    // scores: thread t => head h=t>>4, neighbor j=t&15; 16-wide softmax per head
    {
        const int h = t >> 4;
        const int j = t & 15;
        float s = 0.f;
        #pragma unroll
        for (int d = 0; d < NDH; ++d)
            s = fmaf(qsh[h*NDH + d], KshT[h*NDH + d][j], s);
        s *= 0.25f;
        float mx = s;
        #pragma unroll
        for (int o = 8; o > 0; o >>= 1) mx = fmaxf(mx, __shfl_xor_sync(0xffffffffu, mx, o));
        float p = __expf(s - mx);
        float sum = p;
        #pragma unroll
        for (int o = 8; o > 0; o >>= 1) sum += __shfl_xor_sync(0xffffffffu, sum, o);
        attn[t] = __fdividef(p, sum);
    }
    __syncthreads();

    float o_acc = 0.f;
    const int hb = t & ~15;
    #pragma unroll
    for (int jj = 0; jj < NKNN; ++jj)
        o_acc = fmaf(attn[hb + jj], VshT[t][jj], o_acc);
    g_att[row*NE + t] = o_acc;
}

// ---------------- score GEMM: s = 10*tanh(final_q . emb / sqrt(E)) + mask ----------------
__global__ void __launch_bounds__(256,2) score_gemm_k(
    const float* __restrict__ emb, const float* __restrict__ mask,
    float* __restrict__ outp)
{
    __shared__ __align__(16) float As[32][130];
    __shared__ __align__(16) float Bs[32][260];
    const int b  = blockIdx.z;
    const int m0 = blockIdx.y * 128;
    const int n0 = blockIdx.x * 128;
    const float* A  = g_fq + (size_t)b*NG*NE;
    const float* Bm = emb  + (size_t)b*NN*NE;
    const int tid = threadIdx.x;
    const int tx  = tid & 15, ty = tid >> 4;

    ull acc[4][8];
    #pragma unroll
    for (int p = 0; p < 4; ++p)
        #pragma unroll
        for (int q = 0; q < 8; ++q) acc[p][q] = 0ULL;

    for (int kc = 0; kc < NE; kc += 32) {
        #pragma unroll
        for (int jj = 0; jj < 4; ++jj) {
            int f = tid + jj*256;
            int m = f >> 3, kq = f & 7;
            int gm = m0 + m;
            float4 v = make_float4(0.f,0.f,0.f,0.f);
            if (gm < NG) v = *reinterpret_cast<const float4*>(A + (size_t)gm*NE + kc + kq*4);
            As[kq*4+0][m] = v.x; As[kq*4+1][m] = v.y;
            As[kq*4+2][m] = v.z; As[kq*4+3][m] = v.w;
        }
        #pragma unroll
        for (int jj = 0; jj < 4; ++jj) {
            int f = tid + jj*256;
            int n = f >> 3, kq = f & 7;
            int gn = n0 + n;
            float4 v = make_float4(0.f,0.f,0.f,0.f);
            if (gn < NN) v = *reinterpret_cast<const float4*>(Bm + (size_t)gn*NE + kc + kq*4);
            *reinterpret_cast<float2*>(&Bs[kq*4+0][2*n]) = make_float2(v.x, v.x);
            *reinterpret_cast<float2*>(&Bs[kq*4+1][2*n]) = make_float2(v.y, v.y);
            *reinterpret_cast<float2*>(&Bs[kq*4+2][2*n]) = make_float2(v.z, v.z);
            *reinterpret_cast<float2*>(&Bs[kq*4+3][2*n]) = make_float2(v.w, v.w);
        }
        __syncthreads();
        #pragma unroll
        for (int k = 0; k < 32; ++k) {
            ull a[4], bb[8];
            #pragma unroll
            for (int p = 0; p < 4; ++p)
                a[p] = *reinterpret_cast<const ull*>(&As[k][ty*2 + 32*p]);
            #pragma unroll
            for (int q = 0; q < 8; ++q)
                bb[q] = *reinterpret_cast<const ull*>(&Bs[k][2*(tx + 16*q)]);
            #pragma unroll
            for (int p = 0; p < 4; ++p)
                #pragma unroll
                for (int q = 0; q < 8; ++q) fma2(acc[p][q], a[p], bb[q]);
        }
        __syncthreads();
    }

    const float rsE = 0.08838834764831845f;  // 1/sqrt(128)
    #pragma unroll
    for (int p = 0; p < 4; ++p) {
        int gm = m0 + ty*2 + 32*p;
        #pragma unroll
        for (int q = 0; q < 8; ++q) {
            int gn = n0 + tx + 16*q;
            if (gn >= NN) continue;
            float lo = __uint_as_float((unsigned)(acc[p][q] & 0xffffffffULL));
            float hi = __uint_as_float((unsigned)(acc[p][q] >> 32));
            if (gm < NG) {
                size_t off = ((size_t)b*NG + gm)*NN + gn;
                outp[off] = tanh10(lo*rsE) + mask[off];
            }
            if (gm + 1 < NG) {
                size_t off = ((size_t)b*NG + gm + 1)*NN + gn;
                outp[off] = tanh10(hi*rsE) + mask[off];
            }
        }
    }
}

// ---------------- row softmax over N (in-place on d_out), warp per row ----------------
__global__ void softmax_k(float* __restrict__ outp)
{
    const int warp = threadIdx.x >> 5, lane = threadIdx.x & 31;
    const size_t row = (size_t)blockIdx.x * 8 + warp;
    float* p = outp + row*NN;
    float v[32];
    float mx = -INFINITY;
    #pragma unroll
    for (int i = 0; i < 32; ++i) {
        int n = lane + 32*i;
        v[i] = (n < NN) ? p[n] : -INFINITY;
        mx = fmaxf(mx, v[i]);
    }
    #pragma unroll
    for (int o = 16; o > 0; o >>= 1) mx = fmaxf(mx, __shfl_xor_sync(0xffffffffu, mx, o));
    float s = 0.f;
    #pragma unroll
    for (int i = 0; i < 32; ++i) {
        int n = lane + 32*i;
        float e = (n < NN) ? __expf(v[i] - mx) : 0.f;
        v[i] = e; s += e;
    }
    #pragma unroll
    for (int o = 16; o > 0; o >>= 1) s += __shfl_xor_sync(0xffffffffu, s, o);
    const float inv = __fdividef(1.0f, s);
    #pragma unroll
    for (int i = 0; i < 32; ++i) {
        int n = lane + 32*i;
        if (n < NN) p[n] = v[i]*inv;
    }
}

// ---------------- launch ----------------
extern "C" void kernel_launch(void* const* d_in, const int* in_sizes, int n_in,
                              void* d_out, int out_size)
{
    const int*   last_node = (const int*)  d_in[0];
    const float* coords    = (const float*)d_in[1];
    const float* emb       = (const float*)d_in[2];
    const float* mask      = (const float*)d_in[3];
    const float* Wqg       = (const float*)d_in[4];
    const float* Wq1       = (const float*)d_in[5];
    const float* Wq2       = (const float*)d_in[6];
    const float* Wk        = (const float*)d_in[7];
    const float* Wv        = (const float*)d_in[8];
    const float* Wc        = (const float*)d_in[9];
    const float* bc        = (const float*)d_in[10];
    float* outp = (float*)d_out;

    mean_part_k<<<64, 128>>>(emb);
    qgraph_k<<<NB, 128>>>(Wqg);
    gemm128_k<<<dim3(63, 3), 256>>>(emb, last_node, Wk, Wv, Wq1, Wq2, Wc, bc, 0);
    decode_k<<<NB*NG, 128>>>(last_node, coords, mask);
    gemm128_k<<<dim3(63, 1), 256>>>(emb, last_node, Wk, Wv, Wq1, Wq2, Wc, bc, 3);
    score_gemm_k<<<dim3(8, 8, NB), 256>>>(emb, mask, outp);
    softmax_k<<<NB*NG/8, 256>>>(outp);
}

// round 4
// speedup vs baseline: 1.6407x; 1.1110x over previous
#include <cuda_runtime.h>
#include <math.h>
#include <stdint.h>

#define NB 8
#define NN 1000
#define NG 1000
#define NE 128
#define NDH 16
#define NKNN 16

typedef unsigned long long ull;

// ---------------- scratch (static device arrays; no allocation) ----------------
__device__ float g_part[64*NE];
__device__ float g_qgraph[NB*NE];
__device__ float g_K[NB*NN*NE];
__device__ float g_V[NB*NN*NE];
__device__ float g_q[NB*NG*NE];    // glimpse queries
__device__ float g_att[NB*NG*NE];  // attention output (pre-comb)
__device__ float g_fq[NB*NG*NE];   // final_q

// packed dual-FMA: d = a*b + d elementwise on two fp32 lanes (exact fp32)
__device__ __forceinline__ void fma2(ull &d, ull a, ull b) {
    asm("fma.rn.f32x2 %0, %1, %2, %0;" : "+l"(d) : "l"(a), "l"(b));
}

__device__ __forceinline__ unsigned redux_min_u32(unsigned v) {
    unsigned r;
    asm("redux.sync.min.u32 %0, %1, 0xffffffff;" : "=r"(r) : "r"(v));
    return r;
}

// 10*tanh(x) = 10 - 20/(e^{2x}+1); saturates correctly via __expf inf/0
__device__ __forceinline__ float tanh10(float x) {
    float e = __expf(2.0f*x);
    return 10.0f - __fdividef(20.0f, e + 1.0f);
}

// ---------------- mean: partial sums over n-chunks ----------------
__global__ void mean_part_k(const float* __restrict__ emb)
{
    const int b = blockIdx.x >> 3, c = blockIdx.x & 7;
    const int e = threadIdx.x;
    const float* p = emb + ((size_t)b*NN + c*125)*NE + e;
    float s = 0.f;
    #pragma unroll 5
    for (int i = 0; i < 125; ++i) s += p[(size_t)i*NE];
    g_part[blockIdx.x*NE + e] = s;
}

// ---------------- q_graph = Wqg @ mean ----------------
__global__ void qgraph_k(const float* __restrict__ Wqg)
{
    const int b = blockIdx.x, e = threadIdx.x;
    __shared__ float sm[NE];
    float s = 0.f;
    #pragma unroll
    for (int c = 0; c < 8; ++c) s += g_part[(b*8 + c)*NE + e];
    sm[e] = s * (1.0f/(float)NN);
    __syncthreads();
    const float4* w  = reinterpret_cast<const float4*>(Wqg + e*NE);
    const float4* m4 = reinterpret_cast<const float4*>(sm);
    float acc = 0.f;
    #pragma unroll
    for (int k = 0; k < NE/4; ++k) {
        float4 a = w[k], c = m4[k];
        acc += a.x*c.x + a.y*c.y + a.z*c.z + a.w*c.w;
    }
    g_qgraph[b*NE + e] = acc;
}

// ---------------- fused 128x128 projection GEMMs, FFMA2 inner loop ----------------
__global__ void __launch_bounds__(256,2) gemm128_k(
    const float* __restrict__ emb, const int* __restrict__ gidx,
    const float* __restrict__ Wk,  const float* __restrict__ Wv,
    const float* __restrict__ Wq1, const float* __restrict__ Wq2,
    const float* __restrict__ Wc,  const float* __restrict__ bc,
    int mode_base)
{
    const int mode = mode_base + blockIdx.y;
    const float* A; const float* W; const float* W2 = nullptr; float* C;
    if      (mode == 0) { A = emb;   W = Wk;  C = g_K;  }
    else if (mode == 1) { A = emb;   W = Wv;  C = g_V;  }
    else if (mode == 2) { A = emb;   W = Wq1; W2 = Wq2; C = g_q; }
    else                { A = g_att; W = Wc;  C = g_fq; }

    __shared__ __align__(16) float As[32][130];
    __shared__ __align__(16) float Bs[32][260];   // value-duplicated along n

    const int m0  = blockIdx.x * 128;
    const int tid = threadIdx.x;
    const int tx  = tid & 15, ty = tid >> 4;
    const int M   = NB*NG;   // 8000

    ull acc[4][8];
    #pragma unroll
    for (int p = 0; p < 4; ++p)
        #pragma unroll
        for (int q = 0; q < 8; ++q) acc[p][q] = 0ULL;

    for (int kc = 0; kc < NE; kc += 32) {
        #pragma unroll
        for (int jj = 0; jj < 4; ++jj) {
            int f = tid + jj*256;
            int m = f >> 3, kq = f & 7;
            int gm = m0 + m;
            float4 v = make_float4(0.f,0.f,0.f,0.f);
            if (gm < M) {
                size_t src;
                if (mode == 2) { int b = gm / NG; src = (size_t)b*NN + gidx[gm]; }
                else            src = (size_t)gm;
                v = *reinterpret_cast<const float4*>(A + src*NE + kc + kq*4);
            }
            As[kq*4+0][m] = v.x; As[kq*4+1][m] = v.y;
            As[kq*4+2][m] = v.z; As[kq*4+3][m] = v.w;
        }
        #pragma unroll
        for (int jj = 0; jj < 4; ++jj) {
            int f = tid + jj*256;
            int n = f >> 3, kq = f & 7;
            float4 v = *reinterpret_cast<const float4*>(W + (size_t)n*NE + kc + kq*4);
            if (mode == 2) {
                float4 v2 = *reinterpret_cast<const float4*>(W2 + (size_t)n*NE + kc + kq*4);
                v.x += v2.x; v.y += v2.y; v.z += v2.z; v.w += v2.w;
            }
            *reinterpret_cast<float2*>(&Bs[kq*4+0][2*n]) = make_float2(v.x, v.x);
            *reinterpret_cast<float2*>(&Bs[kq*4+1][2*n]) = make_float2(v.y, v.y);
            *reinterpret_cast<float2*>(&Bs[kq*4+2][2*n]) = make_float2(v.z, v.z);
            *reinterpret_cast<float2*>(&Bs[kq*4+3][2*n]) = make_float2(v.w, v.w);
        }
        __syncthreads();
        #pragma unroll
        for (int k = 0; k < 32; ++k) {
            ull a[4], b[8];
            #pragma unroll
            for (int p = 0; p < 4; ++p)
                a[p] = *reinterpret_cast<const ull*>(&As[k][ty*2 + 32*p]);
            #pragma unroll
            for (int q = 0; q < 8; ++q)
                b[q] = *reinterpret_cast<const ull*>(&Bs[k][2*(tx + 16*q)]);
            #pragma unroll
            for (int p = 0; p < 4; ++p)
                #pragma unroll
                for (int q = 0; q < 8; ++q) fma2(acc[p][q], a[p], b[q]);
        }
        __syncthreads();
    }

    #pragma unroll
    for (int p = 0; p < 4; ++p) {
        int gm = m0 + ty*2 + 32*p;
        #pragma unroll
        for (int q = 0; q < 8; ++q) {
            int n = tx + 16*q;
            float lo = __uint_as_float((unsigned)(acc[p][q] & 0xffffffffULL));
            float hi = __uint_as_float((unsigned)(acc[p][q] >> 32));
            if (gm < M) {
                float v = lo;
                if (mode == 2) v += g_qgraph[(gm/NG)*NE + n];
                if (mode == 3) v += bc[n];
                C[(size_t)gm*NE + n] = v;
            }
            if (gm + 1 < M) {
                float v = hi;
                if (mode == 2) v += g_qgraph[((gm+1)/NG)*NE + n];
                if (mode == 3) v += bc[n];
                C[(size_t)(gm+1)*NE + n] = v;
            }
        }
    }
}

// ---------------- decode: sorted-lane top-16 + glimpse attention ----------------
#define CE(i,j) { ull va=kk[i], vb=kk[j]; bool lt = vb < va; kk[i] = lt ? vb : va; kk[j] = lt ? va : vb; }

__global__ void __launch_bounds__(128) decode_k(const int* __restrict__ last_node,
                         const float* __restrict__ coords,
                         const float* __restrict__ mask)
{
    const int b = blockIdx.x / NG, g = blockIdx.x % NG;
    const int t = threadIdx.x;
    const int lane = t & 31, w = t >> 5;
    __shared__ float KshT[NE][17];
    __shared__ float qsh[NE];
    __shared__ ull   cand[64];

    const size_t row = (size_t)b*NG + g;
    const int idx = last_node[row];
    qsh[t] = g_q[row*NE + t];

    const float2 lc = reinterpret_cast<const float2*>(coords)[(size_t)b*NN + idx];
    const float lsq = lc.x*lc.x + lc.y*lc.y;
    const float* mrow = mask + row*NN;

    // keys: (d2_bits << 32) | n  — exact lexicographic (dist, index) order
    ull kk[8];
    #pragma unroll
    for (int s = 0; s < 8; ++s) {
        int n = t + 128*s;
        ull key = ~0ULL;
        if (n < NN) {
            float2 c = reinterpret_cast<const float2*>(coords)[(size_t)b*NN + n];
            float d2 = lsq + (c.x*c.x + c.y*c.y) - 2.0f*(lc.x*c.x + lc.y*c.y);
            d2 = fmaxf(d2, 0.0f);
            unsigned db = __float_as_uint(d2);       // d2>=0 => bits monotone
            if (mrow[n] == -INFINITY) db = 0x7F800000u;  // +inf
            key = ((ull)db << 32) | (unsigned)n;
        }
        kk[s] = key;
    }

    // sort 8 keys per lane (optimal 19-CE network), ascending
    CE(0,1) CE(2,3) CE(4,5) CE(6,7)
    CE(0,2) CE(1,3) CE(4,6) CE(5,7)
    CE(1,2) CE(5,6) CE(0,4) CE(3,7)
    CE(1,5) CE(2,6)
    CE(1,4) CE(3,6)
    CE(2,4) CE(3,5)
    CE(3,4)

    // per-warp top-16: pop sorted heads via redux + shift-down
    #pragma unroll
    for (int r = 0; r < NKNN; ++r) {
        unsigned mh = (unsigned)(kk[0] >> 32);
        unsigned wmin = redux_min_u32(mh);
        unsigned cd = (mh == wmin) ? (unsigned)kk[0] : 0xFFFFFFFFu;
        unsigned widx = redux_min_u32(cd);
        bool win = (cd == widx);
        if (lane == 0) cand[w*16 + r] = ((ull)wmin << 32) | widx;
        #pragma unroll
        for (int i = 0; i < 7; ++i) kk[i] = win ? kk[i+1] : kk[i];
        kk[7] = win ? ~0ULL : kk[7];
    }
    __syncthreads();

    // every warp merges the 64 candidates (redundant => no 2nd barrier);
    // lane r keeps global winner r in a register
    unsigned knn_reg = 0;
    {
        ull c0 = cand[lane], c1 = cand[lane + 32];
        #pragma unroll
        for (int r = 0; r < NKNN; ++r) {
            bool sel1 = (c1 < c0);
            ull m = sel1 ? c1 : c0;
            unsigned mh = (unsigned)(m >> 32);
            unsigned wmin = redux_min_u32(mh);
            unsigned cd = (mh == wmin) ? (unsigned)m : 0xFFFFFFFFu;
            unsigned widx = redux_min_u32(cd);
            bool win = (cd == widx);
            if (lane == r) knn_reg = widx;
            c1 = (win &&  sel1) ? ~0ULL : c1;
            c0 = (win && !sel1) ? ~0ULL : c0;
        }
    }

    // K rows of the 16 neighbors -> KshT[e][j] (coalesced loads, conflict-free)
    const size_t bNN = (size_t)b*NN;
    #pragma unroll
    for (int j = 0; j < NKNN; ++j) {
        unsigned nj = __shfl_sync(0xffffffffu, knn_reg, j);
        KshT[t][j] = g_K[(bNN + nj)*NE + t];
    }
    __syncthreads();

    // scores: thread t => head h=t>>4, neighbor j=t&15; 16-wide softmax per head
    float av;
    {
        const int h = t >> 4;
        const int j = t & 15;
        float s = 0.f;
        #pragma unroll
        for (int d = 0; d < NDH; ++d)
            s = fmaf(qsh[h*NDH + d], KshT[h*NDH + d][j], s);
        s *= 0.25f;
        float mx = s;
        #pragma unroll
        for (int o = 8; o > 0; o >>= 1) mx = fmaxf(mx, __shfl_xor_sync(0xffffffffu, mx, o));
        float p = __expf(s - mx);
        float sum = p;
        #pragma unroll
        for (int o = 8; o > 0; o >>= 1) sum += __shfl_xor_sync(0xffffffffu, sum, o);
        av = __fdividef(p, sum);
    }

    // out[e=t] = sum_j attn[h(e)][j] * V[nj][e]  (attn + knn via shfl, V direct gmem)
    float o_acc = 0.f;
    const int gbase = lane & 16;
    #pragma unroll
    for (int jj = 0; jj < NKNN; ++jj) {
        unsigned nj = __shfl_sync(0xffffffffu, knn_reg, jj);
        float aj = __shfl_sync(0xffffffffu, av, gbase + jj);
        o_acc = fmaf(aj, g_V[(bNN + nj)*NE + t], o_acc);
    }
    g_att[row*NE + t] = o_acc;
}

// ---------------- score GEMM: s = 10*tanh(final_q . emb / sqrt(E)) + mask ----------------
__global__ void __launch_bounds__(256,2) score_gemm_k(
    const float* __restrict__ emb, const float* __restrict__ mask,
    float* __restrict__ outp)
{
    __shared__ __align__(16) float As[32][130];
    __shared__ __align__(16) float Bs[32][260];
    const int b  = blockIdx.z;
    const int m0 = blockIdx.y * 128;
    const int n0 = blockIdx.x * 128;
    const float* A  = g_fq + (size_t)b*NG*NE;
    const float* Bm = emb  + (size_t)b*NN*NE;
    const int tid = threadIdx.x;
    const int tx  = tid & 15, ty = tid >> 4;

    ull acc[4][8];
    #pragma unroll
    for (int p = 0; p < 4; ++p)
        #pragma unroll
        for (int q = 0; q < 8; ++q) acc[p][q] = 0ULL;

    for (int kc = 0; kc < NE; kc += 32) {
        #pragma unroll
        for (int jj = 0; jj < 4; ++jj) {
            int f = tid + jj*256;
            int m = f >> 3, kq = f & 7;
            int gm = m0 + m;
            float4 v = make_float4(0.f,0.f,0.f,0.f);
            if (gm < NG) v = *reinterpret_cast<const float4*>(A + (size_t)gm*NE + kc + kq*4);
            As[kq*4+0][m] = v.x; As[kq*4+1][m] = v.y;
            As[kq*4+2][m] = v.z; As[kq*4+3][m] = v.w;
        }
        #pragma unroll
        for (int jj = 0; jj < 4; ++jj) {
            int f = tid + jj*256;
            int n = f >> 3, kq = f & 7;
            int gn = n0 + n;
            float4 v = make_float4(0.f,0.f,0.f,0.f);
            if (gn < NN) v = *reinterpret_cast<const float4*>(Bm + (size_t)gn*NE + kc + kq*4);
            *reinterpret_cast<float2*>(&Bs[kq*4+0][2*n]) = make_float2(v.x, v.x);
            *reinterpret_cast<float2*>(&Bs[kq*4+1][2*n]) = make_float2(v.y, v.y);
            *reinterpret_cast<float2*>(&Bs[kq*4+2][2*n]) = make_float2(v.z, v.z);
            *reinterpret_cast<float2*>(&Bs[kq*4+3][2*n]) = make_float2(v.w, v.w);
        }
        __syncthreads();
        #pragma unroll
        for (int k = 0; k < 32; ++k) {
            ull a[4], bb[8];
            #pragma unroll
            for (int p = 0; p < 4; ++p)
                a[p] = *reinterpret_cast<const ull*>(&As[k][ty*2 + 32*p]);
            #pragma unroll
            for (int q = 0; q < 8; ++q)
                bb[q] = *reinterpret_cast<const ull*>(&Bs[k][2*(tx + 16*q)]);
            #pragma unroll
            for (int p = 0; p < 4; ++p)
                #pragma unroll
                for (int q = 0; q < 8; ++q) fma2(acc[p][q], a[p], bb[q]);
        }
        __syncthreads();
    }

    const float rsE = 0.08838834764831845f;  // 1/sqrt(128)
    #pragma unroll
    for (int p = 0; p < 4; ++p) {
        int gm = m0 + ty*2 + 32*p;
        #pragma unroll
        for (int q = 0; q < 8; ++q) {
            int gn = n0 + tx + 16*q;
            if (gn >= NN) continue;
            float lo = __uint_as_float((unsigned)(acc[p][q] & 0xffffffffULL));
            float hi = __uint_as_float((unsigned)(acc[p][q] >> 32));
            if (gm < NG) {
                size_t off = ((size_t)b*NG + gm)*NN + gn;
                outp[off] = tanh10(lo*rsE) + mask[off];
            }
            if (gm + 1 < NG) {
                size_t off = ((size_t)b*NG + gm + 1)*NN + gn;
                outp[off] = tanh10(hi*rsE) + mask[off];
            }
        }
    }
}

// ---------------- row softmax over N (in-place on d_out), warp per row ----------------
__global__ void softmax_k(float* __restrict__ outp)
{
    const int warp = threadIdx.x >> 5, lane = threadIdx.x & 31;
    const size_t row = (size_t)blockIdx.x * 8 + warp;
    float* p = outp + row*NN;
    float v[32];
    float mx = -INFINITY;
    #pragma unroll
    for (int i = 0; i < 32; ++i) {
        int n = lane + 32*i;
        v[i] = (n < NN) ? p[n] : -INFINITY;
        mx = fmaxf(mx, v[i]);
    }
    #pragma unroll
    for (int o = 16; o > 0; o >>= 1) mx = fmaxf(mx, __shfl_xor_sync(0xffffffffu, mx, o));
    float s = 0.f;
    #pragma unroll
    for (int i = 0; i < 32; ++i) {
        int n = lane + 32*i;
        float e = (n < NN) ? __expf(v[i] - mx) : 0.f;
        v[i] = e; s += e;
    }
    #pragma unroll
    for (int o = 16; o > 0; o >>= 1) s += __shfl_xor_sync(0xffffffffu, s, o);
    const float inv = __fdividef(1.0f, s);
    #pragma unroll
    for (int i = 0; i < 32; ++i) {
        int n = lane + 32*i;
        if (n < NN) p[n] = v[i]*inv;
    }
}

// ---------------- launch ----------------
extern "C" void kernel_launch(void* const* d_in, const int* in_sizes, int n_in,
                              void* d_out, int out_size)
{
    const int*   last_node = (const int*)  d_in[0];
    const float* coords    = (const float*)d_in[1];
    const float* emb       = (const float*)d_in[2];
    const float* mask      = (const float*)d_in[3];
    const float* Wqg       = (const float*)d_in[4];
    const float* Wq1       = (const float*)d_in[5];
    const float* Wq2       = (const float*)d_in[6];
    const float* Wk        = (const float*)d_in[7];
    const float* Wv        = (const float*)d_in[8];
    const float* Wc        = (const float*)d_in[9];
    const float* bc        = (const float*)d_in[10];
    float* outp = (float*)d_out;

    mean_part_k<<<64, 128>>>(emb);
    qgraph_k<<<NB, 128>>>(Wqg);
    gemm128_k<<<dim3(63, 3), 256>>>(emb, last_node, Wk, Wv, Wq1, Wq2, Wc, bc, 0);
    decode_k<<<NB*NG, 128>>>(last_node, coords, mask);
    gemm128_k<<<dim3(63, 1), 256>>>(emb, last_node, Wk, Wv, Wq1, Wq2, Wc, bc, 3);
    score_gemm_k<<<dim3(8, 8, NB), 256>>>(emb, mask, outp);
    softmax_k<<<NB*NG/8, 256>>>(outp);
}

// round 5
// speedup vs baseline: 1.8666x; 1.1377x over previous
#include <cuda_runtime.h>
#include <math.h>
#include <stdint.h>

#define NB 8
#define NN 1000
#define NG 1000
#define NE 128
#define NDH 16
#define NKNN 16

typedef unsigned long long ull;

// ---------------- scratch (static device arrays; no allocation) ----------------
__device__ float g_part[64*NE];
__device__ float g_qgraph[NB*NE];
__device__ float g_K[NB*NN*NE];
__device__ float g_V[NB*NN*NE];
__device__ float g_q[NB*NG*NE];    // glimpse queries
__device__ float g_att[NB*NG*NE];  // attention output (pre-comb)
__device__ float g_fq[NB*NG*NE];   // final_q

// packed dual-FMA: d = a*b + d elementwise on two fp32 lanes (exact fp32)
__device__ __forceinline__ void fma2(ull &d, ull a, ull b) {
    asm("fma.rn.f32x2 %0, %1, %2, %0;" : "+l"(d) : "l"(a), "l"(b));
}
// duplicate one fp32 into both halves of a 64-bit operand (1 MOV, alu pipe)
__device__ __forceinline__ ull dup2(float b) {
    ull r;
    asm("mov.b64 %0, {%1, %1};" : "=l"(r) : "f"(b));
    return r;
}

__device__ __forceinline__ unsigned redux_min_u32(unsigned v) {
    unsigned r;
    asm("redux.sync.min.u32 %0, %1, 0xffffffff;" : "=r"(r) : "r"(v));
    return r;
}

// 10*tanh(x) = 10 - 20/(e^{2x}+1); saturates correctly via __expf inf/0
__device__ __forceinline__ float tanh10(float x) {
    float e = __expf(2.0f*x);
    return 10.0f - __fdividef(20.0f, e + 1.0f);
}

// ---------------- mean: partial sums over n-chunks ----------------
__global__ void mean_part_k(const float* __restrict__ emb)
{
    const int b = blockIdx.x >> 3, c = blockIdx.x & 7;
    const int e = threadIdx.x;
    const float* p = emb + ((size_t)b*NN + c*125)*NE + e;
    float s = 0.f;
    #pragma unroll 5
    for (int i = 0; i < 125; ++i) s += p[(size_t)i*NE];
    g_part[blockIdx.x*NE + e] = s;
}

// ---------------- q_graph = Wqg @ mean ----------------
__global__ void qgraph_k(const float* __restrict__ Wqg)
{
    const int b = blockIdx.x, e = threadIdx.x;
    __shared__ float sm[NE];
    float s = 0.f;
    #pragma unroll
    for (int c = 0; c < 8; ++c) s += g_part[(b*8 + c)*NE + e];
    sm[e] = s * (1.0f/(float)NN);
    __syncthreads();
    const float4* w  = reinterpret_cast<const float4*>(Wqg + e*NE);
    const float4* m4 = reinterpret_cast<const float4*>(sm);
    float acc = 0.f;
    #pragma unroll
    for (int k = 0; k < NE/4; ++k) {
        float4 a = w[k], c = m4[k];
        acc += a.x*c.x + a.y*c.y + a.z*c.z + a.w*c.w;
    }
    g_qgraph[b*NE + e] = acc;
}

// ---------------- fused 128x128 projection GEMMs, FFMA2 inner loop ----------------
__global__ void __launch_bounds__(256,2) gemm128_k(
    const float* __restrict__ emb, const int* __restrict__ gidx,
    const float* __restrict__ Wk,  const float* __restrict__ Wv,
    const float* __restrict__ Wq1, const float* __restrict__ Wq2,
    const float* __restrict__ Wc,  const float* __restrict__ bc,
    int mode_base)
{
    const int mode = mode_base + blockIdx.y;
    const float* A; const float* W; const float* W2 = nullptr; float* C;
    if      (mode == 0) { A = emb;   W = Wk;  C = g_K;  }
    else if (mode == 1) { A = emb;   W = Wv;  C = g_V;  }
    else if (mode == 2) { A = emb;   W = Wq1; W2 = Wq2; C = g_q; }
    else                { A = g_att; W = Wc;  C = g_fq; }

    __shared__ __align__(16) float As[32][130];
    __shared__ __align__(16) float Bs[32][129];   // plain; stride 129 => conflict-free 4B stores

    const int m0  = blockIdx.x * 128;
    const int tid = threadIdx.x;
    const int tx  = tid & 15, ty = tid >> 4;
    const int M   = NB*NG;   // 8000

    ull acc[4][8];
    #pragma unroll
    for (int p = 0; p < 4; ++p)
        #pragma unroll
        for (int q = 0; q < 8; ++q) acc[p][q] = 0ULL;

    for (int kc = 0; kc < NE; kc += 32) {
        #pragma unroll
        for (int jj = 0; jj < 4; ++jj) {
            int f = tid + jj*256;
            int m = f >> 3, kq = f & 7;
            int gm = m0 + m;
            float4 v = make_float4(0.f,0.f,0.f,0.f);
            if (gm < M) {
                size_t src;
                if (mode == 2) { int b = gm / NG; src = (size_t)b*NN + gidx[gm]; }
                else            src = (size_t)gm;
                v = *reinterpret_cast<const float4*>(A + src*NE + kc + kq*4);
            }
            As[kq*4+0][m] = v.x; As[kq*4+1][m] = v.y;
            As[kq*4+2][m] = v.z; As[kq*4+3][m] = v.w;
        }
        #pragma unroll
        for (int jj = 0; jj < 4; ++jj) {
            int f = tid + jj*256;
            int n = f >> 3, kq = f & 7;
            float4 v = *reinterpret_cast<const float4*>(W + (size_t)n*NE + kc + kq*4);
            if (mode == 2) {
                float4 v2 = *reinterpret_cast<const float4*>(W2 + (size_t)n*NE + kc + kq*4);
                v.x += v2.x; v.y += v2.y; v.z += v2.z; v.w += v2.w;
            }
            Bs[kq*4+0][n] = v.x;
            Bs[kq*4+1][n] = v.y;
            Bs[kq*4+2][n] = v.z;
            Bs[kq*4+3][n] = v.w;
        }
        __syncthreads();
        #pragma unroll
        for (int k = 0; k < 32; ++k) {
            ull a[4], b[8];
            #pragma unroll
            for (int p = 0; p < 4; ++p)
                a[p] = *reinterpret_cast<const ull*>(&As[k][ty*2 + 32*p]);
            #pragma unroll
            for (int q = 0; q < 8; ++q)
                b[q] = dup2(Bs[k][tx + 16*q]);
            #pragma unroll
            for (int p = 0; p < 4; ++p)
                #pragma unroll
                for (int q = 0; q < 8; ++q) fma2(acc[p][q], a[p], b[q]);
        }
        __syncthreads();
    }

    #pragma unroll
    for (int p = 0; p < 4; ++p) {
        int gm = m0 + ty*2 + 32*p;
        #pragma unroll
        for (int q = 0; q < 8; ++q) {
            int n = tx + 16*q;
            float lo = __uint_as_float((unsigned)(acc[p][q] & 0xffffffffULL));
            float hi = __uint_as_float((unsigned)(acc[p][q] >> 32));
            if (gm < M) {
                float v = lo;
                if (mode == 2) v += g_qgraph[(gm/NG)*NE + n];
                if (mode == 3) v += bc[n];
                C[(size_t)gm*NE + n] = v;
            }
            if (gm + 1 < M) {
                float v = hi;
                if (mode == 2) v += g_qgraph[((gm+1)/NG)*NE + n];
                if (mode == 3) v += bc[n];
                C[(size_t)(gm+1)*NE + n] = v;
            }
        }
    }
}

// ---------------- decode: sorted-lane top-16 + glimpse attention ----------------
#define CE(i,j) { ull va=kk[i], vb=kk[j]; bool lt = vb < va; kk[i] = lt ? vb : va; kk[j] = lt ? va : vb; }

__global__ void __launch_bounds__(128) decode_k(const int* __restrict__ last_node,
                         const float* __restrict__ coords,
                         const float* __restrict__ mask)
{
    const int b = blockIdx.x / NG, g = blockIdx.x % NG;
    const int t = threadIdx.x;
    const int lane = t & 31, w = t >> 5;
    __shared__ float KshT[NE][17];
    __shared__ float qsh[NE];
    __shared__ ull   cand[64];
    __shared__ int   knn_sh[NKNN];

    const size_t row = (size_t)b*NG + g;
    const int idx = last_node[row];
    qsh[t] = g_q[row*NE + t];

    const float2 lc = reinterpret_cast<const float2*>(coords)[(size_t)b*NN + idx];
    const float lsq = lc.x*lc.x + lc.y*lc.y;
    const float* mrow = mask + row*NN;

    // keys: (d2_bits << 32) | n  — exact lexicographic (dist, index) order
    ull kk[8];
    #pragma unroll
    for (int s = 0; s < 8; ++s) {
        int n = t + 128*s;
        ull key = ~0ULL;
        if (n < NN) {
            float2 c = reinterpret_cast<const float2*>(coords)[(size_t)b*NN + n];
            float d2 = lsq + (c.x*c.x + c.y*c.y) - 2.0f*(lc.x*c.x + lc.y*c.y);
            d2 = fmaxf(d2, 0.0f);
            unsigned db = __float_as_uint(d2);       // d2>=0 => bits monotone
            if (mrow[n] == -INFINITY) db = 0x7F800000u;  // +inf
            key = ((ull)db << 32) | (unsigned)n;
        }
        kk[s] = key;
    }

    // sort 8 keys per lane (optimal 19-CE network), ascending
    CE(0,1) CE(2,3) CE(4,5) CE(6,7)
    CE(0,2) CE(1,3) CE(4,6) CE(5,7)
    CE(1,2) CE(5,6) CE(0,4) CE(3,7)
    CE(1,5) CE(2,6)
    CE(1,4) CE(3,6)
    CE(2,4) CE(3,5)
    CE(3,4)

    // per-warp top-16: pop sorted heads via redux; shift bounded by liveness
    #pragma unroll
    for (int r = 0; r < NKNN; ++r) {
        unsigned mh = (unsigned)(kk[0] >> 32);
        unsigned wmin = redux_min_u32(mh);
        unsigned cd = (mh == wmin) ? (unsigned)kk[0] : 0xFFFFFFFFu;
        unsigned widx = redux_min_u32(cd);
        bool win = (cd == widx);
        if (lane == 0) cand[w*16 + r] = ((ull)wmin << 32) | widx;
        const int L = (15 - r < 7) ? (15 - r) : 7;   // only first L slots still live
        #pragma unroll
        for (int i = 0; i < 7; ++i)
            if (i < L) kk[i] = win ? kk[i+1] : kk[i];
        if (L == 7) kk[7] = win ? ~0ULL : kk[7];
    }
    __syncthreads();

    // warp 0 alone merges the 64 candidates into the global top-16
    if (w == 0) {
        ull c0 = cand[lane], c1 = cand[lane + 32];
        #pragma unroll
        for (int r = 0; r < NKNN; ++r) {
            bool sel1 = (c1 < c0);
            ull m = sel1 ? c1 : c0;
            unsigned mh = (unsigned)(m >> 32);
            unsigned wmin = redux_min_u32(mh);
            unsigned cd = (mh == wmin) ? (unsigned)m : 0xFFFFFFFFu;
            unsigned widx = redux_min_u32(cd);
            bool win = (cd == widx);
            if (lane == 0) knn_sh[r] = (int)widx;
            c1 = (win &&  sel1) ? ~0ULL : c1;
            c0 = (win && !sel1) ? ~0ULL : c0;
        }
    }
    __syncthreads();

    // K rows of the 16 neighbors -> KshT[e][j] (coalesced loads, conflict-free)
    const size_t bNN = (size_t)b*NN;
    #pragma unroll
    for (int j = 0; j < NKNN; ++j) {
        int nj = knn_sh[j];
        KshT[t][j] = g_K[(bNN + nj)*NE + t];
    }
    __syncthreads();

    // scores: thread t => head h=t>>4, neighbor j=t&15; 16-wide softmax per head
    float av;
    {
        const int h = t >> 4;
        const int j = t & 15;
        float s = 0.f;
        #pragma unroll
        for (int d = 0; d < NDH; ++d)
            s = fmaf(qsh[h*NDH + d], KshT[h*NDH + d][j], s);
        s *= 0.25f;
        float mx = s;
        #pragma unroll
        for (int o = 8; o > 0; o >>= 1) mx = fmaxf(mx, __shfl_xor_sync(0xffffffffu, mx, o));
        float p = __expf(s - mx);
        float sum = p;
        #pragma unroll
        for (int o = 8; o > 0; o >>= 1) sum += __shfl_xor_sync(0xffffffffu, sum, o);
        av = __fdividef(p, sum);
    }

    // out[e=t] = sum_j attn[h(e)][j] * V[nj][e]  (attn via shfl, V direct gmem)
    float o_acc = 0.f;
    const int gbase = lane & 16;
    #pragma unroll
    for (int jj = 0; jj < NKNN; ++jj) {
        int nj = knn_sh[jj];
        float aj = __shfl_sync(0xffffffffu, av, gbase + jj);
        o_acc = fmaf(aj, g_V[(bNN + nj)*NE + t], o_acc);
    }
    g_att[row*NE + t] = o_acc;
}

// ---------------- score GEMM: s = 10*tanh(final_q . emb / sqrt(E)) + mask ----------------
__global__ void __launch_bounds__(256,2) score_gemm_k(
    const float* __restrict__ emb, const float* __restrict__ mask,
    float* __restrict__ outp)
{
    __shared__ __align__(16) float As[32][130];
    __shared__ __align__(16) float Bs[32][129];
    const int b  = blockIdx.z;
    const int m0 = blockIdx.y * 128;
    const int n0 = blockIdx.x * 128;
    const float* A  = g_fq + (size_t)b*NG*NE;
    const float* Bm = emb  + (size_t)b*NN*NE;
    const int tid = threadIdx.x;
    const int tx  = tid & 15, ty = tid >> 4;

    ull acc[4][8];
    #pragma unroll
    for (int p = 0; p < 4; ++p)
        #pragma unroll
        for (int q = 0; q < 8; ++q) acc[p][q] = 0ULL;

    for (int kc = 0; kc < NE; kc += 32) {
        #pragma unroll
        for (int jj = 0; jj < 4; ++jj) {
            int f = tid + jj*256;
            int m = f >> 3, kq = f & 7;
            int gm = m0 + m;
            float4 v = make_float4(0.f,0.f,0.f,0.f);
            if (gm < NG) v = *reinterpret_cast<const float4*>(A + (size_t)gm*NE + kc + kq*4);
            As[kq*4+0][m] = v.x; As[kq*4+1][m] = v.y;
            As[kq*4+2][m] = v.z; As[kq*4+3][m] = v.w;
        }
        #pragma unroll
        for (int jj = 0; jj < 4; ++jj) {
            int f = tid + jj*256;
            int n = f >> 3, kq = f & 7;
            int gn = n0 + n;
            float4 v = make_float4(0.f,0.f,0.f,0.f);
            if (gn < NN) v = *reinterpret_cast<const float4*>(Bm + (size_t)gn*NE + kc + kq*4);
            Bs[kq*4+0][n] = v.x;
            Bs[kq*4+1][n] = v.y;
            Bs[kq*4+2][n] = v.z;
            Bs[kq*4+3][n] = v.w;
        }
        __syncthreads();
        #pragma unroll
        for (int k = 0; k < 32; ++k) {
            ull a[4], bb[8];
            #pragma unroll
            for (int p = 0; p < 4; ++p)
                a[p] = *reinterpret_cast<const ull*>(&As[k][ty*2 + 32*p]);
            #pragma unroll
            for (int q = 0; q < 8; ++q)
                bb[q] = dup2(Bs[k][tx + 16*q]);
            #pragma unroll
            for (int p = 0; p < 4; ++p)
                #pragma unroll
                for (int q = 0; q < 8; ++q) fma2(acc[p][q], a[p], bb[q]);
        }
        __syncthreads();
    }

    const float rsE = 0.08838834764831845f;  // 1/sqrt(128)
    #pragma unroll
    for (int p = 0; p < 4; ++p) {
        int gm = m0 + ty*2 + 32*p;
        #pragma unroll
        for (int q = 0; q < 8; ++q) {
            int gn = n0 + tx + 16*q;
            if (gn >= NN) continue;
            float lo = __uint_as_float((unsigned)(acc[p][q] & 0xffffffffULL));
            float hi = __uint_as_float((unsigned)(acc[p][q] >> 32));
            if (gm < NG) {
                size_t off = ((size_t)b*NG + gm)*NN + gn;
                outp[off] = tanh10(lo*rsE) + mask[off];
            }
            if (gm + 1 < NG) {
                size_t off = ((size_t)b*NG + gm + 1)*NN + gn;
                outp[off] = tanh10(hi*rsE) + mask[off];
            }
        }
    }
}

// ---------------- row softmax over N (in-place on d_out), warp per row ----------------
__global__ void softmax_k(float* __restrict__ outp)
{
    const int warp = threadIdx.x >> 5, lane = threadIdx.x & 31;
    const size_t row = (size_t)blockIdx.x * 8 + warp;
    float* p = outp + row*NN;
    float v[32];
    float mx = -INFINITY;
    #pragma unroll
    for (int i = 0; i < 32; ++i) {
        int n = lane + 32*i;
        v[i] = (n < NN) ? p[n] : -INFINITY;
        mx = fmaxf(mx, v[i]);
    }
    #pragma unroll
    for (int o = 16; o > 0; o >>= 1) mx = fmaxf(mx, __shfl_xor_sync(0xffffffffu, mx, o));
    float s = 0.f;
    #pragma unroll
    for (int i = 0; i < 32; ++i) {
        int n = lane + 32*i;
        float e = (n < NN) ? __expf(v[i] - mx) : 0.f;
        v[i] = e; s += e;
    }
    #pragma unroll
    for (int o = 16; o > 0; o >>= 1) s += __shfl_xor_sync(0xffffffffu, s, o);
    const float inv = __fdividef(1.0f, s);
    #pragma unroll
    for (int i = 0; i < 32; ++i) {
        int n = lane + 32*i;
        if (n < NN) p[n] = v[i]*inv;
    }
}

// ---------------- launch ----------------
extern "C" void kernel_launch(void* const* d_in, const int* in_sizes, int n_in,
                              void* d_out, int out_size)
{
    const int*   last_node = (const int*)  d_in[0];
    const float* coords    = (const float*)d_in[1];
    const float* emb       = (const float*)d_in[2];
    const float* mask      = (const float*)d_in[3];
    const float* Wqg       = (const float*)d_in[4];
    const float* Wq1       = (const float*)d_in[5];
    const float* Wq2       = (const float*)d_in[6];
    const float* Wk        = (const float*)d_in[7];
    const float* Wv        = (const float*)d_in[8];
    const float* Wc        = (const float*)d_in[9];
    const float* bc        = (const float*)d_in[10];
    float* outp = (float*)d_out;

    mean_part_k<<<64, 128>>>(emb);
    qgraph_k<<<NB, 128>>>(Wqg);
    gemm128_k<<<dim3(63, 3), 256>>>(emb, last_node, Wk, Wv, Wq1, Wq2, Wc, bc, 0);
    decode_k<<<NB*NG, 128>>>(last_node, coords, mask);
    gemm128_k<<<dim3(63, 1), 256>>>(emb, last_node, Wk, Wv, Wq1, Wq2, Wc, bc, 3);
    score_gemm_k<<<dim3(8, 8, NB), 256>>>(emb, mask, outp);
    softmax_k<<<NB*NG/8, 256>>>(outp);
}